// round 17
// baseline (speedup 1.0000x reference)
#include <cuda_runtime.h>
#include <cuda_bf16.h>
#include <math.h>
#include <stdint.h>

#define BB 256
#define NN 128
#define LL 2048
#define DD 64

// bf16x2 pair buffers: pair p of row l holds cols 2p, 2p+1
__device__ uint32_t g_pA[(size_t)BB * LL * 32];
__device__ uint32_t g_pB[(size_t)BB * LL * 32];
__device__ float g_comp[BB * DD];
__device__ float g_prot[BB * DD];
__device__ float g_msum[BB];
__device__ float g_hv[BB * DD];
__device__ uint32_t g_wp[2048];     // W_att bf16 pairs [e][p]
__device__ uint32_t g_kp[3 * 920];  // conv Toeplitz taps per layer

// ---------------- helpers ----------------
__device__ __forceinline__ float tf32r(float x) {
    float r; asm("cvt.rna.tf32.f32 %0, %1;" : "=f"(r) : "f"(x)); return r;
}
__device__ __forceinline__ void mma_tf32(float* c, float a0, float a1, float a2, float a3,
                                         float b0, float b1) {
    asm volatile(
        "mma.sync.aligned.m16n8k8.row.col.f32.tf32.tf32.f32 "
        "{%0,%1,%2,%3}, {%4,%5,%6,%7}, {%8,%9}, {%0,%1,%2,%3};"
        : "+f"(c[0]), "+f"(c[1]), "+f"(c[2]), "+f"(c[3])
        : "r"(__float_as_uint(a0)), "r"(__float_as_uint(a1)),
          "r"(__float_as_uint(a2)), "r"(__float_as_uint(a3)),
          "r"(__float_as_uint(b0)), "r"(__float_as_uint(b1)));
}
__device__ __forceinline__ void mma_bf16(float* c, uint32_t a0, uint32_t a1,
                                         uint32_t a2, uint32_t a3,
                                         uint32_t b0, uint32_t b1) {
    asm volatile(
        "mma.sync.aligned.m16n8k16.row.col.f32.bf16.bf16.f32 "
        "{%0,%1,%2,%3}, {%4,%5,%6,%7}, {%8,%9}, {%0,%1,%2,%3};"
        : "+f"(c[0]), "+f"(c[1]), "+f"(c[2]), "+f"(c[3])
        : "r"(a0), "r"(a1), "r"(a2), "r"(a3), "r"(b0), "r"(b1));
}
__device__ __forceinline__ uint32_t pbf2(float lo, float hi) {
    __nv_bfloat162 h = __floats2bfloat162_rn(lo, hi);
    return *(uint32_t*)&h;
}

// ---------------- prep: pack W_att bf16 + conv tap tables (once) ----------
__global__ void __launch_bounds__(256) pack_k(
    const float* __restrict__ W_att, const float* __restrict__ ck)
{
    const int tid = threadIdx.x;
    for (int idx = tid; idx < 2048; idx += 256) {
        int e = idx >> 5, p = idx & 31;
        g_wp[idx] = pbf2(W_att[e * 64 + 2 * p], W_att[e * 64 + 2 * p + 1]);
    }
    for (int idx = tid; idx < 3 * 920; idx += 256) {
        int layer = idx / 920, r = idx - layer * 920;
        int i = r / 40, rr = r % 40, par = rr / 20, jo = rr % 20;
        int d = 2 * jo - 8 + par;
        const float* kk = ck + layer * 529;
        float v0 = (d >= 0 && d < 23) ? kk[i * 23 + d] : 0.f;
        float v1 = (d + 1 >= 0 && d + 1 < 23) ? kk[i * 23 + d + 1] : 0.f;
        g_kp[idx] = pbf2(v0, v1);
    }
}

// ---------------- hv per batch (after GNN): hv = relu(W_att@comp + b) -----
__global__ void __launch_bounds__(64) hv_prep(
    const float* __restrict__ W_att, const float* __restrict__ b_att)
{
    __shared__ float compS[64];
    const int b = blockIdx.x, tid = threadIdx.x;
    compS[tid] = g_comp[b * 64 + tid];
    __syncthreads();
    float a = b_att[tid];
    const float* wr = W_att + tid * 64;
    #pragma unroll 4
    for (int d = 0; d < 64; d++) a = fmaf(compS[d], wr[d], a);
    g_hv[b * 64 + tid] = fmaxf(a, 0.f);
}

// ---------------- conv: bf16 m16n8k16 Toeplitz, 64-row tiles --------------
#define ST 52
#define CV_SMEM ((86 * ST + 23 * 40) * 4)

__global__ void __launch_bounds__(128) conv_bf16(
    const float* __restrict__ cb,
    int layer, int srcSel, int gather,
    const int* __restrict__ amino, const float* __restrict__ emb)
{
    extern __shared__ uint32_t cs[];
    uint32_t* inS = cs;             // [86][52] bf16x2
    uint32_t* kP  = cs + 86 * ST;   // [23][2 parity][20]

    const uint32_t* inp = srcSel ? g_pB : g_pA;
    uint32_t* outp      = srcSel ? g_pA : g_pB;

    const int b  = blockIdx.y;
    const int h0 = blockIdx.x * 64;
    const int tid = threadIdx.x;

    for (int idx = tid; idx < 86 * ST; idx += 128) inS[idx] = 0u;
    for (int idx = tid; idx < 230; idx += 128)
        ((uint4*)kP)[idx] = ((const uint4*)(g_kp + layer * 920))[idx];

    if (gather) {
        const int* am = amino + b * LL;
        for (int idx = tid; idx < 86 * 16; idx += 128) {
            int s = idx >> 4, q = idx & 15;
            int gh = h0 + s - 11;
            if (gh >= 0 && gh < LL) {
                float4 v = ((const float4*)(emb + (size_t)am[gh] * DD))[q];
                inS[s * ST + 6 + 2 * q]     = pbf2(v.x, v.y);
                inS[s * ST + 6 + 2 * q + 1] = pbf2(v.z, v.w);
            }
        }
    } else {
        const uint32_t* inb = inp + (size_t)b * LL * 32;
        for (int idx = tid; idx < 86 * 8; idx += 128) {
            int s = idx >> 3, q = idx & 7;
            int gh = h0 + s - 11;
            if (gh >= 0 && gh < LL) {
                uint4 v = ((const uint4*)(inb + (size_t)gh * 32))[q];
                uint32_t* p = inS + s * ST + 6 + 4 * q;
                p[0] = v.x; p[1] = v.y; p[2] = v.z; p[3] = v.w;
            }
        }
    }
    __syncthreads();

    const int lane = tid & 31, warp = tid >> 5;
    const int grp = lane >> 2, qd = lane & 3;
    const int mbase = warp * 16;

    float acc[8][4];
    #pragma unroll
    for (int n = 0; n < 8; n++)
        #pragma unroll
        for (int e = 0; e < 4; e++) acc[n][e] = 0.f;

    const uint32_t* Pbase = kP + ((grp & 1) ? 0 : 20);
    const int j0 = (grp & 1) ? (qd + ((7 - grp) >> 1)) : (qd + 3 - (grp >> 1));

    #pragma unroll 1
    for (int i = 0; i < 23; i++) {
        const uint32_t* P = Pbase + i * 40;
        uint32_t b00 = P[j0], b01 = P[j0 + 4], b10 = P[j0 + 8], b11 = P[j0 + 12];
        const uint32_t* r0 = inS + (mbase + grp + i) * ST + qd;
        const uint32_t* r1 = r0 + 8 * ST;
        uint32_t c0 = r0[0], c1 = r1[0];
        #pragma unroll
        for (int g = 0; g < 10; g++) {
            uint32_t n0 = r0[4 * (g + 1)], n1 = r1[4 * (g + 1)];
            if (g < 8)  mma_bf16(acc[g],     c0, c1, n0, n1, b00, b01);
            if (g >= 2) mma_bf16(acc[g - 2], c0, c1, n0, n1, b10, b11);
            c0 = n0; c1 = n1;
        }
    }

    const float bias = cb[layer];
    const int m0 = mbase + grp;
    uint32_t* ob = outp + ((size_t)b * LL + h0) * 32;
    #pragma unroll
    for (int n = 0; n < 8; n++) {
        int pr = 4 * n + qd;
        ob[(size_t)m0 * 32 + pr] =
            pbf2(fmaxf(acc[n][0] + bias, 0.f), fmaxf(acc[n][1] + bias, 0.f));
        ob[(size_t)(m0 + 8) * 32 + pr] =
            pbf2(fmaxf(acc[n][2] + bias, 0.f), fmaxf(acc[n][3] + bias, 0.f));
    }
}

// ---------------- hs GEMM + fused attention pooling (128 rows/block) -------
#define PT 36
// smem carve (u32 units): psT[128*36] | wS[64*36] | hsS[128*69 floats] |
//                         bS[64] hv[64] wrow[128] pp[256] msum[1]
#define HS_PST 0
#define HS_WS  (128 * PT)
#define HS_HSS (HS_WS + 64 * PT)
#define HS_BS  (HS_HSS + 128 * 69)
#define HS_HV  (HS_BS + 64)
#define HS_WR  (HS_HV + 64)
#define HS_PP  (HS_WR + 128)
#define HS_MS  (HS_PP + 256)
#define HS_SMEM ((HS_MS + 1) * 4)

__global__ void __launch_bounds__(256) hs_pool(
    const float* __restrict__ b_att, const float* __restrict__ amino_mask)
{
    extern __shared__ uint32_t hsm[];
    uint32_t* psT = hsm + HS_PST;
    uint32_t* wS  = hsm + HS_WS;
    float* hsS  = (float*)(hsm + HS_HSS);
    float* bS   = (float*)(hsm + HS_BS);
    float* hvS  = (float*)(hsm + HS_HV);
    float* wrow = (float*)(hsm + HS_WR);
    float* pp   = (float*)(hsm + HS_PP);
    float* msum_s = (float*)(hsm + HS_MS);

    const int b  = blockIdx.y;
    const int l0 = blockIdx.x * 128;
    const int tid = threadIdx.x;

    const uint32_t* pb = g_pB + (size_t)b * LL * 32;
    for (int idx = tid; idx < 128 * 8; idx += 256) {
        int s = idx >> 3, q = idx & 7;
        ((uint4*)psT)[s * 9 + q] = ((const uint4*)(pb + (size_t)(l0 + s) * 32))[q];
    }
    for (int idx = tid; idx < 512; idx += 256)
        ((uint4*)wS)[idx] = ((const uint4*)g_wp)[idx];
    if (tid < 64) { bS[tid] = b_att[tid]; hvS[tid] = g_hv[b * 64 + tid]; }
    if (tid == 0) *msum_s = 0.f;
    __syncthreads();

    const int lane = tid & 31, warp = tid >> 5;   // 8 warps
    const int grp = lane >> 2, qd = lane & 3;
    const int mbase = warp * 16;

    float acc[8][4];
    #pragma unroll
    for (int n = 0; n < 8; n++)
        #pragma unroll
        for (int e = 0; e < 4; e++) acc[n][e] = 0.f;

    #pragma unroll
    for (int kc = 0; kc < 4; kc++) {
        const uint32_t* ar0 = psT + (mbase + grp) * PT + 8 * kc + qd;
        const uint32_t* ar1 = ar0 + 8 * PT;
        uint32_t a0 = ar0[0], a1 = ar1[0], a2 = ar0[4], a3 = ar1[4];
        #pragma unroll
        for (int n = 0; n < 8; n++) {
            const uint32_t* wr = wS + (8 * n + grp) * PT + 8 * kc + qd;
            mma_bf16(acc[n], a0, a1, a2, a3, wr[0], wr[4]);
        }
    }

    const float* mk = amino_mask + b * LL;
    const int l = mbase + grp;                    // 0..119
    float m0v = mk[l0 + l], m1v = mk[l0 + l + 8];
    #pragma unroll
    for (int n = 0; n < 8; n++) {
        int e = 8 * n + 2 * qd;
        hsS[l * 69 + e]           = fmaxf(acc[n][0] + bS[e], 0.f) * m0v;
        hsS[l * 69 + e + 1]       = fmaxf(acc[n][1] + bS[e + 1], 0.f) * m0v;
        hsS[(l + 8) * 69 + e]     = fmaxf(acc[n][2] + bS[e], 0.f) * m1v;
        hsS[(l + 8) * 69 + e + 1] = fmaxf(acc[n][3] + bS[e + 1], 0.f) * m1v;
    }
    __syncthreads();

    // per-row attention weight (threads 0-127), mask sum
    if (tid < 128) {
        float wh = 0.f;
        #pragma unroll 4
        for (int d = 0; d < 64; d++) wh = fmaf(hvS[d], hsS[tid * 69 + d], wh);
        wrow[tid] = tanhf(wh);
        float mv = mk[l0 + tid];
        for (int off = 16; off; off >>= 1) mv += __shfl_xor_sync(~0u, mv, off);
        if (lane == 0) atomicAdd(msum_s, mv);
    }
    __syncthreads();

    // pooled sum: 4 quarters of rows x 64 dims
    {
        int dim = tid & 63, quar = tid >> 6;
        float p = 0.f;
        int r0 = quar * 32;
        #pragma unroll 4
        for (int r = r0; r < r0 + 32; r++) p = fmaf(wrow[r], hsS[r * 69 + dim], p);
        pp[quar * 64 + dim] = p;
    }
    __syncthreads();
    if (tid < 64)
        atomicAdd(&g_prot[b * 64 + tid],
                  pp[tid] + pp[64 + tid] + pp[128 + tid] + pp[192 + tid]);
    if (tid == 0) atomicAdd(&g_msum[b], *msum_s);
}

__global__ void zero_prot() {
    int i = blockIdx.x * 256 + threadIdx.x;
    if (i < BB * 64) g_prot[i] = 0.f;
    if (i < BB) g_msum[i] = 0.f;
}

// ---------------- GNN via split-tf32 mma: 1 block/batch, 256 threads ---------
#define GN_SMEM ((8704 + 8448 + 4608 + 64) * 4)

__global__ void __launch_bounds__(256) gnn_mma(
    const int* __restrict__ atoms, const float* __restrict__ atoms_mask,
    const float* __restrict__ adj, const float* __restrict__ emb_fp,
    const float* __restrict__ W_gnn, const float* __restrict__ b_gnn)
{
    extern __shared__ float sg[];
    float* xs  = sg;            // 128*68
    float* hsT = sg + 8704;     // 64*132 (fp32, exact)
    float* wk  = sg + 17152;    // max(64*68, 128*36)
    float* bv  = sg + 21760;    // 64

    const int b = blockIdx.x, tid = threadIdx.x;
    const int lane = tid & 31, warp = tid >> 5;       // 8 warps
    const int grp = lane >> 2, qd = lane & 3;
    const int mbase = warp * 16;

    for (int idx = tid; idx < 128 * 16; idx += 256) {
        int s = idx >> 4, q = idx & 15;
        float4 v = ((const float4*)(emb_fp + (size_t)atoms[b * NN + s] * DD))[q];
        *(float4*)(xs + s * 68 + 4 * q) = v;
    }

    for (int layer = 0; layer < 3; layer++) {
        __syncthreads();
        for (int idx = tid; idx < 64 * 16; idx += 256) {
            int e = idx >> 4, q = idx & 15;
            *(float4*)(wk + e * 68 + 4 * q) =
                ((const float4*)(W_gnn + layer * 4096 + e * 64))[q];
        }
        if (tid < 64) bv[tid] = b_gnn[layer * 64 + tid];
        __syncthreads();

        float acc[8][4];
        #pragma unroll
        for (int n = 0; n < 8; n++)
            #pragma unroll
            for (int e = 0; e < 4; e++) acc[n][e] = 0.f;

        #pragma unroll 1
        for (int ks = 0; ks < 8; ks++) {
            float bh[8][2], bl[8][2];
            #pragma unroll
            for (int n = 0; n < 8; n++) {
                const float* wr = wk + (8 * n + grp) * 68 + 8 * ks + qd;
                float w0 = wr[0], w1 = wr[4];
                bh[n][0] = tf32r(w0); bl[n][0] = tf32r(w0 - bh[n][0]);
                bh[n][1] = tf32r(w1); bl[n][1] = tf32r(w1 - bh[n][1]);
            }
            const float* ar = xs + (mbase + grp) * 68 + 8 * ks + qd;
            float x0 = ar[0], x1 = ar[8 * 68], x2 = ar[4], x3 = ar[8 * 68 + 4];
            float ah0 = tf32r(x0), al0 = tf32r(x0 - ah0);
            float ah1 = tf32r(x1), al1 = tf32r(x1 - ah1);
            float ah2 = tf32r(x2), al2 = tf32r(x2 - ah2);
            float ah3 = tf32r(x3), al3 = tf32r(x3 - ah3);
            #pragma unroll
            for (int n = 0; n < 8; n++) {
                mma_tf32(acc[n], ah0, ah1, ah2, ah3, bh[n][0], bh[n][1]);
                mma_tf32(acc[n], al0, al1, al2, al3, bh[n][0], bh[n][1]);
                mma_tf32(acc[n], ah0, ah1, ah2, ah3, bl[n][0], bl[n][1]);
            }
        }
        {
            int m = mbase + grp;
            #pragma unroll
            for (int n = 0; n < 8; n++) {
                int e = 8 * n + 2 * qd;
                hsT[e * 132 + m]           = fmaxf(acc[n][0] + bv[e], 0.f);
                hsT[(e + 1) * 132 + m]     = fmaxf(acc[n][1] + bv[e + 1], 0.f);
                hsT[e * 132 + m + 8]       = fmaxf(acc[n][2] + bv[e], 0.f);
                hsT[(e + 1) * 132 + m + 8] = fmaxf(acc[n][3] + bv[e + 1], 0.f);
            }
        }

        float acc2[8][4];
        {
            int m = mbase + grp;
            #pragma unroll
            for (int n = 0; n < 8; n++) {
                int c = 8 * n + 2 * qd;
                float2 v = *(float2*)(xs + m * 68 + c);
                acc2[n][0] = v.x; acc2[n][1] = v.y;
                v = *(float2*)(xs + (m + 8) * 68 + c);
                acc2[n][2] = v.x; acc2[n][3] = v.y;
            }
        }
        const float* adjb = adj + (size_t)b * NN * NN;
        #pragma unroll 1
        for (int g4 = 0; g4 < 4; g4++) {
            __syncthreads();
            for (int idx = tid; idx < 128 * 8; idx += 256) {
                int s = idx >> 3, q = idx & 7;
                *(float4*)(wk + s * 36 + 4 * q) =
                    ((const float4*)(adjb + s * 128 + g4 * 32))[q];
            }
            __syncthreads();
            #pragma unroll
            for (int kc = 0; kc < 4; kc++) {
                float bh[8][2], bl[8][2];
                #pragma unroll
                for (int n = 0; n < 8; n++) {
                    const float* hr = hsT + (8 * n + grp) * 132 + g4 * 32 + 8 * kc + qd;
                    float h0 = hr[0], h1 = hr[4];
                    bh[n][0] = tf32r(h0); bl[n][0] = tf32r(h0 - bh[n][0]);
                    bh[n][1] = tf32r(h1); bl[n][1] = tf32r(h1 - bh[n][1]);
                }
                const float* ar = wk + (mbase + grp) * 36 + 8 * kc + qd;
                float x0 = ar[0], x1 = ar[8 * 36], x2 = ar[4], x3 = ar[8 * 36 + 4];
                float ah0 = tf32r(x0), al0 = tf32r(x0 - ah0);
                float ah1 = tf32r(x1), al1 = tf32r(x1 - ah1);
                float ah2 = tf32r(x2), al2 = tf32r(x2 - ah2);
                float ah3 = tf32r(x3), al3 = tf32r(x3 - ah3);
                #pragma unroll
                for (int n = 0; n < 8; n++) {
                    mma_tf32(acc2[n], ah0, ah1, ah2, ah3, bh[n][0], bh[n][1]);
                    mma_tf32(acc2[n], al0, al1, al2, al3, bh[n][0], bh[n][1]);
                    mma_tf32(acc2[n], ah0, ah1, ah2, ah3, bl[n][0], bl[n][1]);
                }
            }
        }
        {
            int m = mbase + grp;
            #pragma unroll
            for (int n = 0; n < 8; n++) {
                int c = 8 * n + 2 * qd;
                *(float2*)(xs + m * 68 + c) = make_float2(acc2[n][0], acc2[n][1]);
                *(float2*)(xs + (m + 8) * 68 + c) = make_float2(acc2[n][2], acc2[n][3]);
            }
        }
    }
    __syncthreads();

    if (tid < DD) {
        float s = 0.f, ms = 0.f;
        for (int n = 0; n < NN; n++) {
            float m = atoms_mask[b * NN + n];
            s += xs[n * 68 + tid] * m;
            ms += m;
        }
        g_comp[b * DD + tid] = s / (ms + 1e-6f);
    }
}

// ---------------- final: cat -> MLP -> out ----------------
__global__ void __launch_bounds__(128) out_fin(
    const float* __restrict__ W_out, const float* __restrict__ b_out,
    const float* __restrict__ W_int, const float* __restrict__ b_int,
    float* __restrict__ out)
{
    __shared__ float cat[128], nxt[128];
    const int b = blockIdx.x, tid = threadIdx.x;
    if (tid < 64) {
        cat[tid] = g_comp[b * 64 + tid];
        cat[64 + tid] = g_prot[b * 64 + tid] / (g_msum[b] + 1e-6f);
    }
    __syncthreads();
    for (int j = 0; j < 2; j++) {
        float a = b_out[j * 128 + tid];
        const float* wr = W_out + j * 16384 + tid * 128;
        #pragma unroll 4
        for (int d = 0; d < 128; d++) a = fmaf(cat[d], wr[d], a);
        nxt[tid] = fmaxf(a, 0.f);
        __syncthreads();
        cat[tid] = nxt[tid];
        __syncthreads();
    }
    if (tid < 2) {
        float a = b_int[tid];
        const float* wr = W_int + tid * 128;
        for (int d = 0; d < 128; d++) a = fmaf(cat[d], wr[d], a);
        out[b * 2 + tid] = a;
    }
}

// ===========================================================================
extern "C" void kernel_launch(void* const* d_in, const int* in_sizes, int n_in,
                              void* d_out, int out_size)
{
    const int*   atoms      = (const int*)  d_in[0];
    const float* atoms_mask = (const float*)d_in[1];
    const float* adjacency  = (const float*)d_in[2];
    const int*   amino      = (const int*)  d_in[3];
    const float* amino_mask = (const float*)d_in[4];
    const float* emb_fp     = (const float*)d_in[5];
    const float* emb_word   = (const float*)d_in[6];
    const float* W_gnn      = (const float*)d_in[7];
    const float* b_gnn      = (const float*)d_in[8];
    const float* conv_k     = (const float*)d_in[9];
    const float* conv_b     = (const float*)d_in[10];
    const float* W_att      = (const float*)d_in[11];
    const float* b_att      = (const float*)d_in[12];
    const float* W_out      = (const float*)d_in[13];
    const float* b_out      = (const float*)d_in[14];
    const float* W_int      = (const float*)d_in[15];
    const float* b_int      = (const float*)d_in[16];
    float* out = (float*)d_out;

    static cudaStream_t s1 = nullptr;
    static cudaEvent_t evF = nullptr, evJ = nullptr;
    if (s1 == nullptr) {
        cudaStreamCreateWithFlags(&s1, cudaStreamNonBlocking);
        cudaEventCreateWithFlags(&evF, cudaEventDisableTiming);
        cudaEventCreateWithFlags(&evJ, cudaEventDisableTiming);
        cudaFuncSetAttribute(gnn_mma,   cudaFuncAttributeMaxDynamicSharedMemorySize, GN_SMEM);
        cudaFuncSetAttribute(conv_bf16, cudaFuncAttributeMaxDynamicSharedMemorySize, CV_SMEM);
        cudaFuncSetAttribute(hs_pool,   cudaFuncAttributeMaxDynamicSharedMemorySize, HS_SMEM);
    }

    // one-time packing (tiny), then fork
    pack_k<<<1, 256>>>(W_att, conv_k);

    cudaEventRecord(evF, 0);
    cudaStreamWaitEvent(s1, evF, 0);

    gnn_mma<<<BB, 256, GN_SMEM, s1>>>(atoms, atoms_mask, adjacency, emb_fp, W_gnn, b_gnn);
    hv_prep<<<BB, 64, 0, s1>>>(W_att, b_att);
    zero_prot<<<64, 256, 0, s1>>>();

    dim3 cgrid(LL / 64, BB);
    conv_bf16<<<cgrid, 128, CV_SMEM>>>(conv_b, 0, 0, 1, amino, emb_word); // emb -> pB
    conv_bf16<<<cgrid, 128, CV_SMEM>>>(conv_b, 1, 1, 0, amino, emb_word); // pB -> pA
    conv_bf16<<<cgrid, 128, CV_SMEM>>>(conv_b, 2, 0, 0, amino, emb_word); // pA -> pB

    cudaEventRecord(evJ, s1);
    cudaStreamWaitEvent(0, evJ, 0);

    dim3 hgrid(LL / 128, BB);
    hs_pool<<<hgrid, 256, HS_SMEM>>>(b_att, amino_mask);  // pB -> pooled g_prot
    out_fin<<<BB, 128>>>(W_out, b_out, W_int, b_int, out);
}